// round 1
// baseline (speedup 1.0000x reference)
#include <cuda_runtime.h>

// Problem dimensions (fixed by setup_inputs)
#define BB 9600      // batch rows (Z)
#define SS 2400      // candidate rows (Y)
#define SPAD 2432    // S padded to multiple of 128
#define FF 4096      // feature dim

// Scratch (device globals: allocation-free rule)
__device__ float g_Zn[(long long)BB * FF];    // normalized Z
__device__ float g_Yn[(long long)SPAD * FF];  // normalized Y, pad rows zeroed
__device__ float g_simL[BB];
__device__ int   g_labels[BB];
__device__ int   g_inv[SS];
__device__ int   g_gt[BB];
__device__ int   g_eqb[BB];
__device__ int   g_hit[2];

// ---------------------------------------------------------------------------
__global__ void init_kernel() {
    int i = blockIdx.x * blockDim.x + threadIdx.x;
    if (i < BB) { g_gt[i] = 0; g_eqb[i] = 0; }
    if (i < SS) g_inv[i] = 0x7FFFFFFF;
    if (i < 2)  g_hit[i] = 0;
}

// L2-normalize rows of src into g_Zn (which=0) or g_Yn (which=1).
// Rows >= rows are zero-filled (padding).
__global__ void normalize_kernel(const float* __restrict__ src, int rows, int which) {
    float* dst = which ? g_Yn : g_Zn;
    int row = blockIdx.x;
    long long base = (long long)row * FF;
    if (row >= rows) {
        for (int c = threadIdx.x; c < FF; c += blockDim.x) dst[base + c] = 0.f;
        return;
    }
    const float* p = src + base;
    __shared__ float red[8];
    __shared__ float s_n;
    float s = 0.f;
    for (int c = threadIdx.x * 4; c < FF; c += blockDim.x * 4) {
        float4 v = *(const float4*)(p + c);
        s += v.x * v.x + v.y * v.y + v.z * v.z + v.w * v.w;
    }
    for (int o = 16; o > 0; o >>= 1) s += __shfl_xor_sync(0xffffffffu, s, o);
    if ((threadIdx.x & 31) == 0) red[threadIdx.x >> 5] = s;
    __syncthreads();
    if (threadIdx.x == 0) {
        float t = 0.f;
        int nw = blockDim.x >> 5;
        for (int w = 0; w < nw; w++) t += red[w];
        float n = sqrtf(t);
        s_n = fmaxf(n, 1e-8f);
    }
    __syncthreads();
    float n = s_n;
    for (int c = threadIdx.x * 4; c < FF; c += blockDim.x * 4) {
        float4 v = *(const float4*)(p + c);
        float4 o;
        o.x = v.x / n; o.y = v.y / n; o.z = v.z / n; o.w = v.w / n;
        *(float4*)(dst + base + c) = o;
    }
}

// inv[test[j]] = min j (first-match semantics of argmax over equality)
__global__ void scatter_kernel(const int* __restrict__ test) {
    int j = blockIdx.x * blockDim.x + threadIdx.x;
    if (j < SS) {
        int v = test[j];
        if (v >= 0 && v < SS) atomicMin(&g_inv[v], j);
    }
}

__global__ void labels_kernel(const int* __restrict__ yidx) {
    int i = blockIdx.x * blockDim.x + threadIdx.x;
    if (i >= BB) return;
    int v = yidx[i];
    int lab = 0;  // argmax of all-False == 0
    if (v >= 0 && v < SS) {
        int t = g_inv[v];
        if (t != 0x7FFFFFFF) lab = t;
    }
    g_labels[i] = lab;
}

// simL[i] = dot(Zn[i], Yn[labels[i]])
__global__ void simL_kernel() {
    int i = blockIdx.x;
    int lab = g_labels[i];
    const float* z = g_Zn + (long long)i * FF;
    const float* y = g_Yn + (long long)lab * FF;
    float s = 0.f;
    for (int c = threadIdx.x * 4; c < FF; c += blockDim.x * 4) {
        float4 a = *(const float4*)(z + c);
        float4 b = *(const float4*)(y + c);
        s += a.x * b.x + a.y * b.y + a.z * b.z + a.w * b.w;
    }
    for (int o = 16; o > 0; o >>= 1) s += __shfl_xor_sync(0xffffffffu, s, o);
    __shared__ float red[8];
    if ((threadIdx.x & 31) == 0) red[threadIdx.x >> 5] = s;
    __syncthreads();
    if (threadIdx.x == 0) {
        float t = 0.f;
        int nw = blockDim.x >> 5;
        for (int w = 0; w < nw; w++) t += red[w];
        g_simL[i] = t;
    }
}

// ---------------------------------------------------------------------------
// Fused SGEMM + rank-count epilogue. fp32 via packed fma.rn.f32x2 (2 FMA/issue).
#define BM 128
#define BN 128
#define BK 8

__device__ __forceinline__ unsigned long long pack2(float lo, float hi) {
    unsigned long long r;
    asm("mov.b64 %0, {%1, %2};" : "=l"(r) : "f"(lo), "f"(hi));
    return r;
}
__device__ __forceinline__ void unpack2(unsigned long long v, float& lo, float& hi) {
    asm("mov.b64 {%0, %1}, %2;" : "=f"(lo), "=f"(hi) : "l"(v));
}
__device__ __forceinline__ unsigned long long fma2(unsigned long long a,
                                                   unsigned long long b,
                                                   unsigned long long c) {
    unsigned long long d;
    asm("fma.rn.f32x2 %0, %1, %2, %3;" : "=l"(d) : "l"(a), "l"(b), "l"(c));
    return d;
}

__global__ __launch_bounds__(256, 2) void gemm_count_kernel() {
    __shared__ float As[BK][BM + 4];
    __shared__ float Bs[BK][BN + 4];
    __shared__ float sL[BM];
    __shared__ int   sLab[BM];

    int tid = threadIdx.x;
    int tx = tid & 15;        // column group 0..15  (8 cols each)
    int ty = tid >> 4;        // row group    0..15  (8 rows each)
    int brow = blockIdx.y * BM;
    int bcol = blockIdx.x * BN;

    if (tid < BM) {
        sL[tid]   = g_simL[brow + tid];
        sLab[tid] = g_labels[brow + tid];
    }

    // Global->SMEM load mapping: 256 threads x float4 per tile side
    int lr = tid >> 1;          // 0..127 : row of A tile / row (=col j) of B tile
    int lk = (tid & 1) * 4;     // 0 or 4 : k offset
    const float* Aptr = g_Zn + (long long)(brow + lr) * FF + lk;
    const float* Bptr = g_Yn + (long long)(bcol + lr) * FF + lk;

    float4 aReg = *(const float4*)(Aptr);
    float4 bReg = *(const float4*)(Bptr);

    unsigned long long acc[8][4];  // 8 rows x 4 f32x2 pairs (8 cols)
#pragma unroll
    for (int i = 0; i < 8; i++)
#pragma unroll
        for (int j = 0; j < 4; j++) acc[i][j] = 0ull;  // bits(+0.f,+0.f)

    for (int kt = 0; kt < FF; kt += BK) {
        As[lk + 0][lr] = aReg.x; As[lk + 1][lr] = aReg.y;
        As[lk + 2][lr] = aReg.z; As[lk + 3][lr] = aReg.w;
        Bs[lk + 0][lr] = bReg.x; Bs[lk + 1][lr] = bReg.y;
        Bs[lk + 2][lr] = bReg.z; Bs[lk + 3][lr] = bReg.w;
        __syncthreads();

        if (kt + BK < FF) {  // prefetch next tile into registers
            aReg = *(const float4*)(Aptr + kt + BK);
            bReg = *(const float4*)(Bptr + kt + BK);
        }

#pragma unroll
        for (int k = 0; k < BK; k++) {
            float4 a0 = *(const float4*)&As[k][ty * 8];
            float4 a1 = *(const float4*)&As[k][ty * 8 + 4];
            ulonglong2 b0 = *(const ulonglong2*)&Bs[k][tx * 8];
            ulonglong2 b1 = *(const ulonglong2*)&Bs[k][tx * 8 + 4];
            float a[8] = {a0.x, a0.y, a0.z, a0.w, a1.x, a1.y, a1.z, a1.w};
#pragma unroll
            for (int i = 0; i < 8; i++) {
                unsigned long long aa = pack2(a[i], a[i]);
                acc[i][0] = fma2(aa, b0.x, acc[i][0]);
                acc[i][1] = fma2(aa, b0.y, acc[i][1]);
                acc[i][2] = fma2(aa, b1.x, acc[i][2]);
                acc[i][3] = fma2(aa, b1.y, acc[i][3]);
            }
        }
        __syncthreads();
    }

    // Epilogue: count elements beating sim[label] (rank computation), no store of sims
#pragma unroll
    for (int i = 0; i < 8; i++) {
        int rl  = ty * 8 + i;
        float sl = sL[rl];
        int lab  = sLab[rl];
        int gt = 0, eqb = 0;
#pragma unroll
        for (int jj = 0; jj < 4; jj++) {
            float lo, hi;
            unpack2(acc[i][jj], lo, hi);
            int c0 = bcol + tx * 8 + jj * 2;
            int c1 = c0 + 1;
            if (c0 < SS && c0 != lab) {
                if (lo > sl) gt++;
                else if (lo == sl && c0 < lab) eqb++;
            }
            if (c1 < SS && c1 != lab) {
                if (hi > sl) gt++;
                else if (hi == sl && c1 < lab) eqb++;
            }
        }
        if (gt)  atomicAdd(&g_gt[brow + rl], gt);
        if (eqb) atomicAdd(&g_eqb[brow + rl], eqb);
    }
}

// ---------------------------------------------------------------------------
__global__ void finalize_kernel() {
    int i = blockIdx.x * blockDim.x + threadIdx.x;
    if (i >= BB) return;
    int r = g_gt[i] + g_eqb[i];  // rank of label within row
    if (r < 1) atomicAdd(&g_hit[0], 1);
    if (r < 5) atomicAdd(&g_hit[1], 1);
}

__global__ void writeout_kernel(float* __restrict__ out) {
    out[0] = (float)g_hit[0] / (float)BB;
    out[1] = (float)g_hit[1] / (float)BB;
}

// ---------------------------------------------------------------------------
extern "C" void kernel_launch(void* const* d_in, const int* in_sizes, int n_in,
                              void* d_out, int out_size) {
    (void)in_sizes; (void)n_in; (void)out_size;
    const float* Z    = (const float*)d_in[0];
    const int*   yidx = (const int*)d_in[1];
    const float* Y    = (const float*)d_in[2];
    const int*   test = (const int*)d_in[3];
    float* out = (float*)d_out;

    init_kernel<<<(BB + 255) / 256, 256>>>();
    normalize_kernel<<<BB, 256>>>(Z, BB, 0);
    normalize_kernel<<<SPAD, 256>>>(Y, SS, 1);
    scatter_kernel<<<(SS + 255) / 256, 256>>>(test);
    labels_kernel<<<(BB + 255) / 256, 256>>>(yidx);
    simL_kernel<<<BB, 128>>>();

    dim3 grid(SPAD / BN, BB / BM);
    gemm_count_kernel<<<grid, 256>>>();

    finalize_kernel<<<(BB + 255) / 256, 256>>>();
    writeout_kernel<<<1, 1>>>(out);
}

// round 4
// speedup vs baseline: 2.6602x; 2.6602x over previous
#include <cuda_runtime.h>
#include <cuda_bf16.h>
#include <cstdint>

// Problem dimensions (fixed by setup_inputs)
#define BB 9600      // batch rows (Z)
#define SS 2400      // candidate rows (Y)
#define SPAD 2432    // S padded to multiple of 128
#define FF 4096      // feature dim
#define NCH (FF / 32)  // 32-elem K chunks for GEMM

// ---------------------------------------------------------------------------
// Scratch (device globals: allocation-free rule). 2-way bf16 split.
__device__ __nv_bfloat16 g_Zh[(size_t)BB * FF];
__device__ __nv_bfloat16 g_Zm[(size_t)BB * FF];
__device__ __nv_bfloat16 g_Yh[(size_t)SPAD * FF];
__device__ __nv_bfloat16 g_Ym[(size_t)SPAD * FF];
__device__ float g_Znorm[BB];
__device__ float g_Ynorm[SS];
__device__ float g_simL[BB];
__device__ int   g_labels[BB];
__device__ int   g_inv[SS];
__device__ int   g_gt[BB];
__device__ int   g_eqb[BB];
__device__ int   g_hit[2];

// ---------------------------------------------------------------------------
__global__ void init_kernel() {
    int i = blockIdx.x * blockDim.x + threadIdx.x;
    if (i < BB) { g_gt[i] = 0; g_eqb[i] = 0; }
    if (i < SS) g_inv[i] = 0x7FFFFFFF;
    if (i < 2)  g_hit[i] = 0;
}

__device__ __forceinline__ uint32_t pack_bf2(__nv_bfloat16 a, __nv_bfloat16 b) {
    __nv_bfloat162 t = __halves2bfloat162(a, b);
    return *reinterpret_cast<uint32_t*>(&t);
}

// Normalize row, split each normalized value into 2 bf16 components (h, m).
__global__ void norm_split_kernel(const float* __restrict__ src, int rows, int which) {
    int row = blockIdx.x;
    int tid = threadIdx.x;  // 128 threads
    size_t base = (size_t)row * FF;
    __nv_bfloat16* H = which ? g_Yh : g_Zh;
    __nv_bfloat16* M = which ? g_Ym : g_Zm;

    if (row >= rows) {  // zero padding rows (Y only)
        for (int j = 0; j < 8; j++) {
            size_t off = base + tid * 4 + j * 512;
            *(uint2*)(H + off) = make_uint2(0, 0);
            *(uint2*)(M + off) = make_uint2(0, 0);
        }
        return;
    }

    float4 v[8];
    float s = 0.f;
#pragma unroll
    for (int j = 0; j < 8; j++) {
        v[j] = *(const float4*)(src + base + tid * 4 + j * 512);
        s += v[j].x * v[j].x + v[j].y * v[j].y + v[j].z * v[j].z + v[j].w * v[j].w;
    }
    for (int o = 16; o > 0; o >>= 1) s += __shfl_xor_sync(0xffffffffu, s, o);
    __shared__ float red[4];
    __shared__ float s_n;
    if ((tid & 31) == 0) red[tid >> 5] = s;
    __syncthreads();
    if (tid == 0) {
        float t = red[0] + red[1] + red[2] + red[3];
        s_n = fmaxf(sqrtf(t), 1e-8f);
        if (which == 0) g_Znorm[row] = s_n;
        else            g_Ynorm[row] = s_n;
    }
    __syncthreads();
    float n = s_n;

#pragma unroll
    for (int j = 0; j < 8; j++) {
        size_t off = base + tid * 4 + j * 512;
        float x[4] = {v[j].x / n, v[j].y / n, v[j].z / n, v[j].w / n};
        __nv_bfloat16 h[4], m[4];
#pragma unroll
        for (int e = 0; e < 4; e++) {
            h[e] = __float2bfloat16(x[e]);
            float r1 = x[e] - __bfloat162float(h[e]);
            m[e] = __float2bfloat16(r1);
        }
        *(uint2*)(H + off) = make_uint2(pack_bf2(h[0], h[1]), pack_bf2(h[2], h[3]));
        *(uint2*)(M + off) = make_uint2(pack_bf2(m[0], m[1]), pack_bf2(m[2], m[3]));
    }
}

// ---------------------------------------------------------------------------
__global__ void scatter_kernel(const int* __restrict__ test) {
    int j = blockIdx.x * blockDim.x + threadIdx.x;
    if (j < SS) {
        int v = test[j];
        if (v >= 0 && v < SS) atomicMin(&g_inv[v], j);
    }
}

__global__ void labels_kernel(const int* __restrict__ yidx) {
    int i = blockIdx.x * blockDim.x + threadIdx.x;
    if (i >= BB) return;
    int v = yidx[i];
    int lab = 0;
    if (v >= 0 && v < SS) {
        int t = g_inv[v];
        if (t != 0x7FFFFFFF) lab = t;
    }
    g_labels[i] = lab;
}

// simL[i] = dot(Z[i], Y[lab]) / (|Z[i]| * |Y[lab]|)   (full fp32)
__global__ void simL_kernel(const float* __restrict__ Z, const float* __restrict__ Y) {
    int i = blockIdx.x;
    int tid = threadIdx.x;  // 128
    int lab = g_labels[i];
    const float* z = Z + (size_t)i * FF;
    const float* y = Y + (size_t)lab * FF;
    float s = 0.f;
    for (int c = tid * 4; c < FF; c += 512) {
        float4 a = *(const float4*)(z + c);
        float4 b = *(const float4*)(y + c);
        s += a.x * b.x + a.y * b.y + a.z * b.z + a.w * b.w;
    }
    for (int o = 16; o > 0; o >>= 1) s += __shfl_xor_sync(0xffffffffu, s, o);
    __shared__ float red[4];
    if ((tid & 31) == 0) red[tid >> 5] = s;
    __syncthreads();
    if (tid == 0) {
        float t = red[0] + red[1] + red[2] + red[3];
        g_simL[i] = t / (g_Znorm[i] * g_Ynorm[lab]);
    }
}

// ---------------------------------------------------------------------------
// Fused bf16 HMMA GEMM (3 split products: Ah*Bh + Ah*Bm + Am*Bh, fp32 accum)
// + rank-count epilogue. Tile 128x128, BK=32, double-buffered cp.async.
#define TILE_B  8192                 // 128 rows x 32 bf16 (64B)
#define CHUNK_B (4 * TILE_B)         // Ah Am Bh Bm
#define SMEM_DYN (2 * CHUNK_B)       // 64 KB

// swizzled byte offset within a tile: row r (0..127), 16B-chunk c (0..3)
__device__ __forceinline__ uint32_t swz(int r, int c) {
    return (uint32_t)(r * 64 + ((c ^ ((r >> 1) & 3)) << 4));
}

static __device__ __forceinline__ uint32_t cvta_s(const void* p) {
    uint32_t a;
    asm("{ .reg .u64 t; cvta.to.shared.u64 t, %1; cvt.u32.u64 %0, t; }" : "=r"(a) : "l"(p));
    return a;
}

__device__ __forceinline__ void ldsm_x4(uint32_t* r, uint32_t addr) {
    asm volatile("ldmatrix.sync.aligned.m8n8.x4.shared.b16 {%0,%1,%2,%3}, [%4];"
                 : "=r"(r[0]), "=r"(r[1]), "=r"(r[2]), "=r"(r[3]) : "r"(addr));
}

__device__ __forceinline__ void mma16816(float* c, const uint32_t* a, uint32_t b0, uint32_t b1) {
    asm volatile(
        "mma.sync.aligned.m16n8k16.row.col.f32.bf16.bf16.f32 "
        "{%0,%1,%2,%3}, {%4,%5,%6,%7}, {%8,%9}, {%0,%1,%2,%3};"
        : "+f"(c[0]), "+f"(c[1]), "+f"(c[2]), "+f"(c[3])
        : "r"(a[0]), "r"(a[1]), "r"(a[2]), "r"(a[3]), "r"(b0), "r"(b1));
}

extern __shared__ char dsm[];

__device__ __forceinline__ void fill_chunk(uint32_t bufbase, int c, int tid,
                                           const __nv_bfloat16* const* srcs) {
#pragma unroll
    for (int t = 0; t < 4; t++) {
        const __nv_bfloat16* sb = srcs[t] + c * 32;
#pragma unroll
        for (int j = 0; j < 2; j++) {
            int idx = tid + j * 256;        // 512 16B ops per tile
            int r = idx >> 2, ck = idx & 3;
            const void* src = sb + (size_t)r * FF + ck * 8;
            uint32_t dst = bufbase + t * TILE_B + swz(r, ck);
            asm volatile("cp.async.cg.shared.global [%0], [%1], 16;" :: "r"(dst), "l"(src));
        }
    }
    asm volatile("cp.async.commit_group;" ::: "memory");
}

__global__ __launch_bounds__(256, 2) void gemm_count_kernel() {
    int tid = threadIdx.x;
    int lane = tid & 31, wid = tid >> 5;
    int warp_m = wid & 3;          // 4 warps along M, 32 rows each
    int warp_n = wid >> 2;         // 2 warps along N, 64 cols each
    int brow = blockIdx.y * 128;
    int bcol = blockIdx.x * 128;
    uint32_t smem = cvta_s(dsm);

    const __nv_bfloat16* srcs[4] = {
        g_Zh + (size_t)brow * FF, g_Zm + (size_t)brow * FF,
        g_Yh + (size_t)bcol * FF, g_Ym + (size_t)bcol * FF};

    float acc[2][8][4];
#pragma unroll
    for (int i = 0; i < 2; i++)
#pragma unroll
        for (int j = 0; j < 8; j++)
#pragma unroll
            for (int v = 0; v < 4; v++) acc[i][j][v] = 0.f;

    fill_chunk(smem, 0, tid, srcs);
    fill_chunk(smem + CHUNK_B, 1, tid, srcs);

    // Precompute per-lane ldmatrix row/chunk components
    int a_r = warp_m * 32 + (lane & 15);        // + i*16
    int b_r = warp_n * 64 + (lane & 15);        // + g*16
    int csel = lane >> 4;                        // 16B chunk within k16: +ks*2

    for (int c = 0; c < NCH; c++) {
        uint32_t buf = smem + (c & 1) * CHUNK_B;
        if (c < NCH - 1) asm volatile("cp.async.wait_group 1;" ::: "memory");
        else             asm volatile("cp.async.wait_group 0;" ::: "memory");
        __syncthreads();

        uint32_t tA[3] = {buf + 0 * TILE_B, buf + 0 * TILE_B, buf + 1 * TILE_B};  // Ah Ah Am
        uint32_t tB[3] = {buf + 2 * TILE_B, buf + 3 * TILE_B, buf + 2 * TILE_B};  // Bh Bm Bh
#pragma unroll
        for (int p = 0; p < 3; p++) {
#pragma unroll
            for (int ks = 0; ks < 2; ks++) {
                uint32_t a[2][4], b[4][4];
#pragma unroll
                for (int i = 0; i < 2; i++)
                    ldsm_x4(a[i], tA[p] + swz(a_r + i * 16, ks * 2 + csel));
#pragma unroll
                for (int g = 0; g < 4; g++)
                    ldsm_x4(b[g], tB[p] + swz(b_r + g * 16, ks * 2 + csel));
#pragma unroll
                for (int i = 0; i < 2; i++)
#pragma unroll
                    for (int jj = 0; jj < 8; jj++) {
                        int g = jj >> 1, w = jj & 1;
                        mma16816(acc[i][jj], a[i], b[g][w], b[g][2 + w]);
                    }
            }
        }
        __syncthreads();
        if (c + 2 < NCH) fill_chunk(buf, c + 2, tid, srcs);
    }

    // Epilogue: rank counting. acc[i][jj][v]: row = warp_m*32+i*16+(lane>>2)+8*(v>>1),
    // col = warp_n*64 + jj*8 + (lane&3)*2 + (v&1)
#pragma unroll
    for (int i = 0; i < 2; i++) {
#pragma unroll
        for (int h = 0; h < 2; h++) {
            int row = brow + warp_m * 32 + i * 16 + (lane >> 2) + h * 8;
            float sl = g_simL[row];
            int lab = g_labels[row];
            int gt = 0, eqb = 0;
#pragma unroll
            for (int jj = 0; jj < 8; jj++) {
#pragma unroll
                for (int w = 0; w < 2; w++) {
                    int col = bcol + warp_n * 64 + jj * 8 + (lane & 3) * 2 + w;
                    float v = acc[i][jj][h * 2 + w];
                    if (col < SS && col != lab) {
                        if (v > sl) gt++;
                        else if (v == sl && col < lab) eqb++;
                    }
                }
            }
            gt  += __shfl_xor_sync(0xffffffffu, gt, 1);
            gt  += __shfl_xor_sync(0xffffffffu, gt, 2);
            eqb += __shfl_xor_sync(0xffffffffu, eqb, 1);
            eqb += __shfl_xor_sync(0xffffffffu, eqb, 2);
            if ((lane & 3) == 0) {
                if (gt)  atomicAdd(&g_gt[row], gt);
                if (eqb) atomicAdd(&g_eqb[row], eqb);
            }
        }
    }
}

// ---------------------------------------------------------------------------
__global__ void finalize_kernel() {
    int i = blockIdx.x * blockDim.x + threadIdx.x;
    if (i >= BB) return;
    int r = g_gt[i] + g_eqb[i];
    if (r < 1) atomicAdd(&g_hit[0], 1);
    if (r < 5) atomicAdd(&g_hit[1], 1);
}

__global__ void writeout_kernel(float* __restrict__ out) {
    out[0] = (float)g_hit[0] / (float)BB;
    out[1] = (float)g_hit[1] / (float)BB;
}

// ---------------------------------------------------------------------------
extern "C" void kernel_launch(void* const* d_in, const int* in_sizes, int n_in,
                              void* d_out, int out_size) {
    (void)in_sizes; (void)n_in; (void)out_size;
    const float* Z    = (const float*)d_in[0];
    const int*   yidx = (const int*)d_in[1];
    const float* Y    = (const float*)d_in[2];
    const int*   test = (const int*)d_in[3];
    float* out = (float*)d_out;

    cudaFuncSetAttribute(gemm_count_kernel,
                         cudaFuncAttributeMaxDynamicSharedMemorySize, SMEM_DYN);

    init_kernel<<<(BB + 255) / 256, 256>>>();
    norm_split_kernel<<<BB, 128>>>(Z, BB, 0);
    norm_split_kernel<<<SPAD, 128>>>(Y, SS, 1);
    scatter_kernel<<<(SS + 255) / 256, 256>>>(test);
    labels_kernel<<<(BB + 255) / 256, 256>>>(yidx);
    simL_kernel<<<BB, 128>>>(Z, Y);

    dim3 grid(SPAD / 128, BB / 128);
    gemm_count_kernel<<<grid, 256, SMEM_DYN>>>();

    finalize_kernel<<<(BB + 255) / 256, 256>>>();
    writeout_kernel<<<1, 1>>>(out);
}

// round 5
// speedup vs baseline: 2.7047x; 1.0167x over previous
#include <cuda_runtime.h>
#include <cuda_bf16.h>
#include <cstdint>

// Problem dimensions (fixed by setup_inputs)
#define BB 9600      // batch rows (Z)
#define SS 2400      // candidate rows (Y)
#define SPAD 2432    // S padded to multiple of 128
#define FF 4096      // feature dim
#define NCH (FF / 32)  // 32-elem K chunks for GEMM

// ---------------------------------------------------------------------------
// Scratch (device globals: allocation-free rule). 2-way bf16 split.
__device__ __nv_bfloat16 g_Zh[(size_t)BB * FF];
__device__ __nv_bfloat16 g_Zm[(size_t)BB * FF];
__device__ __nv_bfloat16 g_Yh[(size_t)SPAD * FF];
__device__ __nv_bfloat16 g_Ym[(size_t)SPAD * FF];
__device__ float g_Znorm[BB];
__device__ float g_Ynorm[SS];
__device__ float g_simL[BB];
__device__ int   g_labels[BB];
__device__ int   g_inv[SS];
__device__ int   g_gt[BB];
__device__ int   g_eqb[BB];
__device__ int   g_hit[2];

// ---------------------------------------------------------------------------
__global__ void init_kernel() {
    int i = blockIdx.x * blockDim.x + threadIdx.x;
    if (i < BB) { g_gt[i] = 0; g_eqb[i] = 0; }
    if (i < SS) g_inv[i] = 0x7FFFFFFF;
    if (i < 2)  g_hit[i] = 0;
}

__device__ __forceinline__ uint32_t pack_bf2(__nv_bfloat16 a, __nv_bfloat16 b) {
    __nv_bfloat162 t = __halves2bfloat162(a, b);
    return *reinterpret_cast<uint32_t*>(&t);
}

// Normalize row, split into 2 bf16 components (h, m). One launch covers Z and Y.
__global__ void norm_split_kernel(const float* __restrict__ Zsrc,
                                  const float* __restrict__ Ysrc) {
    int row = blockIdx.x;
    int tid = threadIdx.x;  // 128 threads
    const float* src;
    __nv_bfloat16 *H, *M;
    int which;
    if (row < BB) {
        src = Zsrc; H = g_Zh; M = g_Zm; which = 0;
    } else {
        row -= BB;
        src = Ysrc; H = g_Yh; M = g_Ym; which = 1;
    }
    size_t base = (size_t)row * FF;

    if (which == 1 && row >= SS) {  // zero padding rows (Y only)
        for (int j = 0; j < 8; j++) {
            size_t off = base + tid * 4 + j * 512;
            *(uint2*)(H + off) = make_uint2(0, 0);
            *(uint2*)(M + off) = make_uint2(0, 0);
        }
        return;
    }

    float4 v[8];
    float s = 0.f;
#pragma unroll
    for (int j = 0; j < 8; j++) {
        v[j] = *(const float4*)(src + base + tid * 4 + j * 512);
        s += v[j].x * v[j].x + v[j].y * v[j].y + v[j].z * v[j].z + v[j].w * v[j].w;
    }
    for (int o = 16; o > 0; o >>= 1) s += __shfl_xor_sync(0xffffffffu, s, o);
    __shared__ float red[4];
    __shared__ float s_n;
    if ((tid & 31) == 0) red[tid >> 5] = s;
    __syncthreads();
    if (tid == 0) {
        float t = red[0] + red[1] + red[2] + red[3];
        s_n = fmaxf(sqrtf(t), 1e-8f);
        if (which == 0) g_Znorm[row] = s_n;
        else            g_Ynorm[row] = s_n;
    }
    __syncthreads();
    float n = s_n;

#pragma unroll
    for (int j = 0; j < 8; j++) {
        size_t off = base + tid * 4 + j * 512;
        float x[4] = {v[j].x / n, v[j].y / n, v[j].z / n, v[j].w / n};
        __nv_bfloat16 h[4], m[4];
#pragma unroll
        for (int e = 0; e < 4; e++) {
            h[e] = __float2bfloat16(x[e]);
            float r1 = x[e] - __bfloat162float(h[e]);
            m[e] = __float2bfloat16(r1);
        }
        *(uint2*)(H + off) = make_uint2(pack_bf2(h[0], h[1]), pack_bf2(h[2], h[3]));
        *(uint2*)(M + off) = make_uint2(pack_bf2(m[0], m[1]), pack_bf2(m[2], m[3]));
    }
}

// ---------------------------------------------------------------------------
__global__ void scatter_kernel(const int* __restrict__ test) {
    int j = blockIdx.x * blockDim.x + threadIdx.x;
    if (j < SS) {
        int v = test[j];
        if (v >= 0 && v < SS) atomicMin(&g_inv[v], j);
    }
}

__global__ void labels_kernel(const int* __restrict__ yidx) {
    int i = blockIdx.x * blockDim.x + threadIdx.x;
    if (i >= BB) return;
    int v = yidx[i];
    int lab = 0;
    if (v >= 0 && v < SS) {
        int t = g_inv[v];
        if (t != 0x7FFFFFFF) lab = t;
    }
    g_labels[i] = lab;
}

// simL[i] = dot(Z[i], Y[lab]) / (|Z[i]| * |Y[lab]|)   (full fp32)
__global__ void simL_kernel(const float* __restrict__ Z, const float* __restrict__ Y) {
    int i = blockIdx.x;
    int tid = threadIdx.x;  // 128
    int lab = g_labels[i];
    const float* z = Z + (size_t)i * FF;
    const float* y = Y + (size_t)lab * FF;
    float s = 0.f;
    for (int c = tid * 4; c < FF; c += 512) {
        float4 a = *(const float4*)(z + c);
        float4 b = *(const float4*)(y + c);
        s += a.x * b.x + a.y * b.y + a.z * b.z + a.w * b.w;
    }
    for (int o = 16; o > 0; o >>= 1) s += __shfl_xor_sync(0xffffffffu, s, o);
    __shared__ float red[4];
    if ((tid & 31) == 0) red[tid >> 5] = s;
    __syncthreads();
    if (tid == 0) {
        float t = red[0] + red[1] + red[2] + red[3];
        g_simL[i] = t / (g_Znorm[i] * g_Ynorm[lab]);
    }
}

// ---------------------------------------------------------------------------
// Fused bf16 HMMA GEMM (3 split products: Ah*Bh + Ah*Bm + Am*Bh, fp32 accum)
// + rank-count epilogue. Tile 128x128, BK=32, 3-stage cp.async pipeline,
// 4 warps with 64x64 warp tiles (128 threads).
#define TILE_B  8192                 // 128 rows x 32 bf16 (64B)
#define STAGE_B (4 * TILE_B)         // Ah Am Bh Bm per stage (32 KB)
#define NSTAGE 3
#define SMEM_DYN (NSTAGE * STAGE_B)  // 96 KB

// swizzled byte offset within a tile: row r (0..127), 16B-chunk c (0..3)
__device__ __forceinline__ uint32_t swz(int r, int c) {
    return (uint32_t)(r * 64 + ((c ^ ((r >> 1) & 3)) << 4));
}

static __device__ __forceinline__ uint32_t cvta_s(const void* p) {
    uint32_t a;
    asm("{ .reg .u64 t; cvta.to.shared.u64 t, %1; cvt.u32.u64 %0, t; }" : "=r"(a) : "l"(p));
    return a;
}

__device__ __forceinline__ void ldsm_x4(uint32_t* r, uint32_t addr) {
    asm volatile("ldmatrix.sync.aligned.m8n8.x4.shared.b16 {%0,%1,%2,%3}, [%4];"
                 : "=r"(r[0]), "=r"(r[1]), "=r"(r[2]), "=r"(r[3]) : "r"(addr));
}

__device__ __forceinline__ void mma16816(float* c, const uint32_t* a, uint32_t b0, uint32_t b1) {
    asm volatile(
        "mma.sync.aligned.m16n8k16.row.col.f32.bf16.bf16.f32 "
        "{%0,%1,%2,%3}, {%4,%5,%6,%7}, {%8,%9}, {%0,%1,%2,%3};"
        : "+f"(c[0]), "+f"(c[1]), "+f"(c[2]), "+f"(c[3])
        : "r"(a[0]), "r"(a[1]), "r"(a[2]), "r"(a[3]), "r"(b0), "r"(b1));
}

extern __shared__ char dsm[];

__device__ __forceinline__ void fill_chunk(uint32_t stagebase, int c, int tid,
                                           const __nv_bfloat16* const* srcs) {
#pragma unroll
    for (int t = 0; t < 4; t++) {
        const __nv_bfloat16* sb = srcs[t] + c * 32;
#pragma unroll
        for (int j = 0; j < 4; j++) {
            int idx = tid + j * 128;        // 512 16B ops per tile, 128 threads
            int r = idx >> 2, ck = idx & 3;
            const void* src = sb + (size_t)r * FF + ck * 8;
            uint32_t dst = stagebase + t * TILE_B + swz(r, ck);
            asm volatile("cp.async.cg.shared.global [%0], [%1], 16;" :: "r"(dst), "l"(src));
        }
    }
    asm volatile("cp.async.commit_group;" ::: "memory");
}

__global__ __launch_bounds__(128, 2) void gemm_count_kernel() {
    int tid = threadIdx.x;
    int lane = tid & 31, wid = tid >> 5;
    int warp_m = wid & 1;          // 2 warps along M, 64 rows each
    int warp_n = wid >> 1;         // 2 warps along N, 64 cols each
    int brow = blockIdx.y * 128;
    int bcol = blockIdx.x * 128;
    uint32_t smem = cvta_s(dsm);

    const __nv_bfloat16* srcs[4] = {
        g_Zh + (size_t)brow * FF, g_Zm + (size_t)brow * FF,
        g_Yh + (size_t)bcol * FF, g_Ym + (size_t)bcol * FF};

    float acc[4][8][4];
#pragma unroll
    for (int i = 0; i < 4; i++)
#pragma unroll
        for (int j = 0; j < 8; j++)
#pragma unroll
            for (int v = 0; v < 4; v++) acc[i][j][v] = 0.f;

    fill_chunk(smem + 0 * STAGE_B, 0, tid, srcs);
    fill_chunk(smem + 1 * STAGE_B, 1, tid, srcs);

    // Per-lane ldmatrix row/chunk components
    int a_r = warp_m * 64 + (lane & 15);        // + i*16
    int b_r = warp_n * 64 + (lane & 15);        // + g*16
    int csel = lane >> 4;                        // 16B chunk within k16: +ks*2

    int stage = 0;
    for (int c = 0; c < NCH; c++) {
        uint32_t buf = smem + stage * STAGE_B;
        if (c < NCH - 2) asm volatile("cp.async.wait_group 1;" ::: "memory");
        else             asm volatile("cp.async.wait_group 0;" ::: "memory");
        __syncthreads();

        // prefetch stage c+2 (stage slot (stage+2)%3, consumed at chunk c-1)
        if (c + 2 < NCH) {
            int ns = stage + 2; if (ns >= NSTAGE) ns -= NSTAGE;
            fill_chunk(smem + ns * STAGE_B, c + 2, tid, srcs);
        }

        uint32_t tA[3] = {buf + 0 * TILE_B, buf + 0 * TILE_B, buf + 1 * TILE_B};  // Ah Ah Am
        uint32_t tB[3] = {buf + 2 * TILE_B, buf + 3 * TILE_B, buf + 2 * TILE_B};  // Bh Bm Bh
#pragma unroll
        for (int p = 0; p < 3; p++) {
#pragma unroll
            for (int ks = 0; ks < 2; ks++) {
                uint32_t a[4][4], b[4][4];
#pragma unroll
                for (int i = 0; i < 4; i++)
                    ldsm_x4(a[i], tA[p] + swz(a_r + i * 16, ks * 2 + csel));
#pragma unroll
                for (int g = 0; g < 4; g++)
                    ldsm_x4(b[g], tB[p] + swz(b_r + g * 16, ks * 2 + csel));
#pragma unroll
                for (int i = 0; i < 4; i++)
#pragma unroll
                    for (int jj = 0; jj < 8; jj++) {
                        int g = jj >> 1, w = jj & 1;
                        mma16816(acc[i][jj], a[i], b[g][w], b[g][2 + w]);
                    }
            }
        }
        stage++; if (stage >= NSTAGE) stage -= NSTAGE;
    }

    // Epilogue: rank counting. acc[i][jj][v]: row = warp_m*64+i*16+(lane>>2)+8*(v>>1),
    // col = warp_n*64 + jj*8 + (lane&3)*2 + (v&1)
#pragma unroll
    for (int i = 0; i < 4; i++) {
#pragma unroll
        for (int h = 0; h < 2; h++) {
            int row = brow + warp_m * 64 + i * 16 + (lane >> 2) + h * 8;
            float sl = g_simL[row];
            int lab = g_labels[row];
            int gt = 0, eqb = 0;
#pragma unroll
            for (int jj = 0; jj < 8; jj++) {
#pragma unroll
                for (int w = 0; w < 2; w++) {
                    int col = bcol + warp_n * 64 + jj * 8 + (lane & 3) * 2 + w;
                    float v = acc[i][jj][h * 2 + w];
                    if (col < SS && col != lab) {
                        if (v > sl) gt++;
                        else if (v == sl && col < lab) eqb++;
                    }
                }
            }
            gt  += __shfl_xor_sync(0xffffffffu, gt, 1);
            gt  += __shfl_xor_sync(0xffffffffu, gt, 2);
            eqb += __shfl_xor_sync(0xffffffffu, eqb, 1);
            eqb += __shfl_xor_sync(0xffffffffu, eqb, 2);
            if ((lane & 3) == 0) {
                if (gt)  atomicAdd(&g_gt[row], gt);
                if (eqb) atomicAdd(&g_eqb[row], eqb);
            }
        }
    }
}

// ---------------------------------------------------------------------------
__global__ void finalize_kernel() {
    int i = blockIdx.x * blockDim.x + threadIdx.x;
    if (i >= BB) return;
    int r = g_gt[i] + g_eqb[i];
    if (r < 1) atomicAdd(&g_hit[0], 1);
    if (r < 5) atomicAdd(&g_hit[1], 1);
}

__global__ void writeout_kernel(float* __restrict__ out) {
    out[0] = (float)g_hit[0] / (float)BB;
    out[1] = (float)g_hit[1] / (float)BB;
}

// ---------------------------------------------------------------------------
extern "C" void kernel_launch(void* const* d_in, const int* in_sizes, int n_in,
                              void* d_out, int out_size) {
    (void)in_sizes; (void)n_in; (void)out_size;
    const float* Z    = (const float*)d_in[0];
    const int*   yidx = (const int*)d_in[1];
    const float* Y    = (const float*)d_in[2];
    const int*   test = (const int*)d_in[3];
    float* out = (float*)d_out;

    cudaFuncSetAttribute(gemm_count_kernel,
                         cudaFuncAttributeMaxDynamicSharedMemorySize, SMEM_DYN);

    init_kernel<<<(BB + 255) / 256, 256>>>();
    norm_split_kernel<<<BB + SPAD, 128>>>(Z, Y);
    scatter_kernel<<<(SS + 255) / 256, 256>>>(test);
    labels_kernel<<<(BB + 255) / 256, 256>>>(yidx);
    simL_kernel<<<BB, 128>>>(Z, Y);

    dim3 grid(SPAD / 128, BB / 128);
    gemm_count_kernel<<<grid, 128, SMEM_DYN>>>();

    finalize_kernel<<<(BB + 255) / 256, 256>>>();
    writeout_kernel<<<1, 1>>>(out);
}